// round 17
// baseline (speedup 1.0000x reference)
#include <cuda_runtime.h>
#include <cuda_pipeline_primitives.h>
#include <cstdint>

// Spatial GCN (24x24 grid, adj = D^-1 A + I => 5-point stencil) + weight
// + BatchNorm2d(train) + LeakyReLU(0.2), fused into TWO kernels.
//
// R17: the kernel boundary replaces the cross-CTA rendezvous.
//  K1: 288-thread CTAs (4 per channel, 45-reg cap -> 5 CTAs/SM), smem-staged
//      stencil computed ONCE, raw y streamed to out, per-CTA (sum,sq)
//      published to g_part. No spin, no counters -- CTAs retire instantly,
//      so waves overlap naturally.
//  K2: streaming normalize: every thread derives scale/bias from the 8
//      broadcast partials (no reduction, no barrier), __ldcs-reads the
//      L2-resident y, applies BN+LeakyReLU, writes in place.
// DRAM traffic stays 151MB (x in, out final); the y round-trip lives in L2.

#define GRID_N  24
#define NN      576
#define NQ      144              // float4 quads per plane
#define BATCH   64
#define CSPLIT  4                // CTAs per channel
#define PLANES  (BATCH / CSPLIT) // 16 planes per CTA
#define PPC     4                // planes per chunk (2 per thread)
#define NCHUNK  (PLANES / PPC)   // 4
#define NTHR    288              // 2 plane-slots x 144 quads
#define BN_EPS  1e-4f
#define SLOPE   0.2f
#define MAXC    512

// per-(channel, rank) partial sums; overwritten by K1 before K2 reads them
__device__ float g_part[MAXC * CSPLIT * 2];

__device__ __forceinline__ float invdeg(int i, int j) {
    const int d = 2 + (int)(i > 0 && i < GRID_N - 1) + (int)(j > 0 && j < GRID_N - 1);
    return (d == 2) ? 0.5f : ((d == 3) ? (1.f / 3.f) : 0.25f);
}

// ======================= K1: stencil + raw y + partials =====================
__global__ __launch_bounds__(NTHR, 5)
void gcn_stats_kernel(const float* __restrict__ x,
                      const float* __restrict__ weight,
                      float* __restrict__ out,
                      int C)
{
    __shared__ float buf[PLANES * NN];         // 36864 B (x, read-only)
    __shared__ float red[24];

    const int c    = blockIdx.x >> 2;
    const int rank = blockIdx.x & 3;           // 0..3
    const int t    = threadIdx.x;              // 0..287
    const int lane = t & 31;
    const int ph   = t / NQ;                   // plane-slot 0..1
    const int q    = t - ph * NQ;              // quad 0..143
    const int row  = q / 6;
    const int col4 = q - row * 6;
    const int l0   = 4 * q;

    const unsigned planeStride = (unsigned)C * NQ;           // float4 units
    const unsigned base0 = (unsigned)(rank * PLANES) * planeStride
                         + (unsigned)c * NQ + q;             // local plane 0

    // ---- prologue: 4 cp.async groups, 2 planes per thread per group ----
    const float4* __restrict__ x4 = (const float4*)x;
    float4* buf4 = (float4*)buf;
#pragma unroll
    for (int s = 0; s < NCHUNK; ++s) {
#pragma unroll
        for (int h = 0; h < 2; ++h) {
            const int lp = s * PPC + ph + h * 2;             // local plane
            __pipeline_memcpy_async(&buf4[(unsigned)lp * NQ + q],
                                    x4 + (base0 + (unsigned)lp * planeStride), 16);
        }
        __pipeline_commit();
    }

    // ---- analytic coefficients folded with weight ----
    const float4 w4 = ((const float4*)(weight + (size_t)c * NN))[q];
    float cL[4], cR[4], cU[4], cD[4];
#pragma unroll
    for (int e = 0; e < 4; ++e) {
        const int j = 4 * col4 + e;
        const float we = (e == 0) ? w4.x : (e == 1) ? w4.y : (e == 2) ? w4.z : w4.w;
        cL[e] = (j > 0)           ? invdeg(row, j - 1) * we : 0.f;
        cR[e] = (j < GRID_N - 1)  ? invdeg(row, j + 1) * we : 0.f;
        cU[e] = (row > 0)         ? invdeg(row - 1, j) * we : 0.f;
        cD[e] = (row < GRID_N -1) ? invdeg(row + 1, j) * we : 0.f;
    }
    const int oL = (col4 > 0) ? l0 - 1 : l0;
    const int oR = (col4 < 5) ? l0 + 4 : l0;
    const int qU = (row > 0) ? q - 6 : q;
    const int qD = (row < GRID_N - 1) ? q + 6 : q;

    float4* __restrict__ out4 = (float4*)out;

#define DO_STENCIL(LP, Y)                                                     \
    {                                                                         \
        const float*  xb  = buf + (unsigned)(LP) * NN;                        \
        const float4* xb4 = (const float4*)xb;                                \
        const float4 ctr = xb4[q];                                            \
        const float4 up  = xb4[qU];                                           \
        const float4 dn  = xb4[qD];                                           \
        const float  lft = xb[oL];                                            \
        const float  rgt = xb[oR];                                            \
        Y.x = w4.x*ctr.x; Y.x = fmaf(cL[0], lft,   Y.x); Y.x = fmaf(cR[0], ctr.y, Y.x); \
        Y.x = fmaf(cU[0], up.x, Y.x); Y.x = fmaf(cD[0], dn.x, Y.x);           \
        Y.y = w4.y*ctr.y; Y.y = fmaf(cL[1], ctr.x, Y.y); Y.y = fmaf(cR[1], ctr.z, Y.y); \
        Y.y = fmaf(cU[1], up.y, Y.y); Y.y = fmaf(cD[1], dn.y, Y.y);           \
        Y.z = w4.z*ctr.z; Y.z = fmaf(cL[2], ctr.y, Y.z); Y.z = fmaf(cR[2], ctr.w, Y.z); \
        Y.z = fmaf(cU[2], up.z, Y.z); Y.z = fmaf(cD[2], dn.z, Y.z);           \
        Y.w = w4.w*ctr.w; Y.w = fmaf(cL[3], ctr.z, Y.w); Y.w = fmaf(cR[3], rgt, Y.w);   \
        Y.w = fmaf(cU[3], up.w, Y.w); Y.w = fmaf(cD[3], dn.w, Y.w);           \
    }

    // ---- stats pass: stencil once, raw y straight to out ----
    float sum = 0.f, sq = 0.f;
#pragma unroll
    for (int ch = 0; ch < NCHUNK; ++ch) {
        __pipeline_wait_prior(NCHUNK - 1 - ch);
        __syncthreads();                       // chunk ch resident (read-only)
        const int lpA = ch * PPC + ph;
        const int lpB = lpA + 2;

        float4 yA, yB;
        DO_STENCIL(lpA, yA);
        DO_STENCIL(lpB, yB);

        sum += (yA.x + yA.y) + (yA.z + yA.w);
        sq = fmaf(yA.x, yA.x, sq); sq = fmaf(yA.y, yA.y, sq);
        sq = fmaf(yA.z, yA.z, sq); sq = fmaf(yA.w, yA.w, sq);
        sum += (yB.x + yB.y) + (yB.z + yB.w);
        sq = fmaf(yB.x, yB.x, sq); sq = fmaf(yB.y, yB.y, sq);
        sq = fmaf(yB.z, yB.z, sq); sq = fmaf(yB.w, yB.w, sq);

        out4[base0 + (unsigned)lpA * planeStride] = yA;   // raw y -> L2
        out4[base0 + (unsigned)lpB * planeStride] = yB;
    }

    // ---- block reduction, publish partial ----
#pragma unroll
    for (int off = 16; off > 0; off >>= 1) {
        sum += __shfl_down_sync(0xffffffffu, sum, off);
        sq  += __shfl_down_sync(0xffffffffu, sq,  off);
    }
    const int warp = t >> 5;                   // 9 warps
    if (lane == 0) { red[warp] = sum; red[12 + warp] = sq; }
    __syncthreads();
    if (t == 0) {
        float s = 0.f, qq = 0.f;
#pragma unroll
        for (int wi = 0; wi < NTHR / 32; ++wi) { s += red[wi]; qq += red[12 + wi]; }
        float* slot = g_part + ((unsigned)(c * CSPLIT + rank)) * 2;
        slot[0] = s; slot[1] = qq;
    }
}

// ======================= K2: normalize + LeakyReLU ==========================
__global__ __launch_bounds__(NTHR, 8)
void gcn_apply_kernel(const float* __restrict__ gamma,
                      const float* __restrict__ beta,
                      float* __restrict__ out,
                      int C)
{
    const int c    = blockIdx.x >> 2;
    const int rank = blockIdx.x & 3;
    const int t    = threadIdx.x;
    const int ph   = t / NQ;
    const int q    = t - ph * NQ;

    const unsigned planeStride = (unsigned)C * NQ;
    const unsigned base0 = (unsigned)(rank * PLANES) * planeStride
                         + (unsigned)c * NQ + q;

    // every thread derives scale/bias from the 8 broadcast partials
    const float* base = g_part + (unsigned)(c * CSPLIT) * 2;
    float st = 0.f, qt = 0.f;
#pragma unroll
    for (int r = 0; r < CSPLIT; ++r) {
        st += __ldg(base + 2 * r);
        qt += __ldg(base + 2 * r + 1);
    }
    const float inv_n = 1.f / (float)(BATCH * NN);
    const float mean = st * inv_n;
    const float var  = fmaf(qt, inv_n, -mean * mean);
    const float rstd = rsqrtf(var + BN_EPS);
    const float sc   = __ldg(gamma + c) * rstd;
    const float bi   = fmaf(-mean, sc, __ldg(beta + c));

    float4* __restrict__ out4 = (float4*)out;
#pragma unroll
    for (int k = 0; k < PLANES / 2; ++k) {     // 8 planes per thread
        const int lp = 2 * k + ph;
        const unsigned idx = base0 + (unsigned)lp * planeStride;
        float4 v = __ldcs(out4 + idx);         // y: L2-resident, evict-first
        v.x = fmaf(v.x, sc, bi); v.y = fmaf(v.y, sc, bi);
        v.z = fmaf(v.z, sc, bi); v.w = fmaf(v.w, sc, bi);
        v.x = (v.x >= 0.f) ? v.x : SLOPE * v.x;
        v.y = (v.y >= 0.f) ? v.y : SLOPE * v.y;
        v.z = (v.z >= 0.f) ? v.z : SLOPE * v.z;
        v.w = (v.w >= 0.f) ? v.w : SLOPE * v.w;
        out4[idx] = v;
    }
}

extern "C" void kernel_launch(void* const* d_in, const int* in_sizes, int n_in,
                              void* d_out, int out_size)
{
    const float* x      = (const float*)d_in[0];
    const float* weight = (const float*)d_in[2];
    const float* gamma  = (const float*)d_in[3];
    const float* beta   = (const float*)d_in[4];
    float* out = (float*)d_out;

    const int C = in_sizes[2] / NN;            // 512
    gcn_stats_kernel<<<C * CSPLIT, NTHR>>>(x, weight, out, C);
    gcn_apply_kernel<<<C * CSPLIT, NTHR>>>(gamma, beta, out, C);
}